// round 1
// baseline (speedup 1.0000x reference)
#include <cuda_runtime.h>
#include <cstdint>

// ---------------- problem constants ----------------
#define BB 2048
#define FF 512
#define MM 16
#define HH 32
#define WW 32
#define PD 64
#define KS 11
#define KK (KS*KS)        // 121
#define HWN (HH*WW)       // 1024
#define XDIM (FF+PD)      // 576
#define WVDIM (KK*MM)     // 1936

// ---------------- scratch (device globals; allocation-free) ----------------
__device__ float g_X [(size_t)BB*XDIM];        // 4.7 MB
__device__ float g_C1[(size_t)BB*256];
__device__ float g_C2[(size_t)BB*128];
__device__ float g_WV[(size_t)BB*WVDIM];       // 15.9 MB
__device__ float g_Y1[(size_t)BB*128*HWN];     // 1.07 GB
__device__ float g_Y2[(size_t)BB*64*HWN];      // 537 MB
__device__ float g_P [(size_t)BB*576];

// ---------------- stage 0: build X = [features | pos_encoding] ----------------
__global__ void build_x_kernel(const float* __restrict__ feat,
                               const float* __restrict__ gaze,
                               float* __restrict__ X)
{
    int b = blockIdx.x;
    int t = threadIdx.x;  // 576 threads
    float v;
    if (t < FF) {
        v = feat[(size_t)b*FF + t];
    } else {
        int j = t - FF;          // 0..63
        int axis = j >> 5;       // 0: x, 1: y
        int w = j & 31;          // 0..31 within enc
        int i = w >> 1;          // 0..15 freq index
        float p = gaze[b*2 + axis];
        // div[i] = exp(-(2i) * ln(10000)/32)
        float dv = expf(-(float)(2*i) * (9.210340371976184f / 32.0f));
        float a = p * dv;
        v = (w & 1) ? cosf(a) : sinf(a);
    }
    X[(size_t)b*XDIM + t] = v;
}

// ---------------- generic tiled GEMM: C = act(A[MxK] @ W[KxN] + bias) ----------------
// BM=BN=64, BK=16, 256 threads, 4x4 per thread. K multiple of 16, M multiple of 64.
__global__ void gemm_kernel(const float* __restrict__ A,
                            const float* __restrict__ W,
                            const float* __restrict__ bias,
                            float* __restrict__ C,
                            int Mdim, int Ndim, int Kdim, int relu)
{
    __shared__ float As[16][64];
    __shared__ float Bs[16][64];
    int bm0 = blockIdx.y * 64;
    int bn0 = blockIdx.x * 64;
    int t = threadIdx.x;
    int ty = t >> 4, tx = t & 15;
    float acc[4][4] = {};

    for (int k0 = 0; k0 < Kdim; k0 += 16) {
        // A tile (64x16), store transposed into As[kk][m]
        {
            int m  = t >> 2;
            int kk = (t & 3) * 4;
            float4 a4 = *reinterpret_cast<const float4*>(&A[(size_t)(bm0 + m)*Kdim + k0 + kk]);
            As[kk+0][m] = a4.x; As[kk+1][m] = a4.y;
            As[kk+2][m] = a4.z; As[kk+3][m] = a4.w;
        }
        // B tile (16x64)
        {
            int r = t >> 4;
            int c = (t & 15) * 4;
            int gn = bn0 + c;
            float4 b4;
            if (gn + 3 < Ndim) {
                b4 = *reinterpret_cast<const float4*>(&W[(size_t)(k0 + r)*Ndim + gn]);
            } else {
                b4.x = (gn+0 < Ndim) ? W[(size_t)(k0+r)*Ndim + gn+0] : 0.f;
                b4.y = (gn+1 < Ndim) ? W[(size_t)(k0+r)*Ndim + gn+1] : 0.f;
                b4.z = (gn+2 < Ndim) ? W[(size_t)(k0+r)*Ndim + gn+2] : 0.f;
                b4.w = (gn+3 < Ndim) ? W[(size_t)(k0+r)*Ndim + gn+3] : 0.f;
            }
            *reinterpret_cast<float4*>(&Bs[r][c]) = b4;
        }
        __syncthreads();
        #pragma unroll
        for (int kk = 0; kk < 16; kk++) {
            float4 a = *reinterpret_cast<const float4*>(&As[kk][ty*4]);
            float4 b = *reinterpret_cast<const float4*>(&Bs[kk][tx*4]);
            float av[4] = {a.x, a.y, a.z, a.w};
            float bv[4] = {b.x, b.y, b.z, b.w};
            #pragma unroll
            for (int j = 0; j < 4; j++)
                #pragma unroll
                for (int i = 0; i < 4; i++)
                    acc[j][i] += av[j] * bv[i];
        }
        __syncthreads();
    }
    #pragma unroll
    for (int j = 0; j < 4; j++) {
        int row = bm0 + ty*4 + j;
        #pragma unroll
        for (int i = 0; i < 4; i++) {
            int col = bn0 + tx*4 + i;
            if (col < Ndim) {
                float v = acc[j][i] + bias[col];
                if (relu) v = fmaxf(v, 0.f);
                C[(size_t)row*Ndim + col] = v;
            }
        }
    }
}

// ---------------- stage: geometry + gather + strength gate + scatter update ----------------
// one block per batch, 128 threads (thread k handles neighbor k<121)
__global__ void scatter_kernel(const float* __restrict__ cell,
                               const float* __restrict__ gaze,
                               const float* __restrict__ WV,
                               const float* __restrict__ ws1,
                               const float* __restrict__ bs1,
                               const float* __restrict__ ws2,
                               const float* __restrict__ bs2,
                               float* __restrict__ upd)
{
    int b = blockIdx.x;
    int t = threadIdx.x;

    __shared__ float s_ws1[32*64];
    __shared__ float s_bs1[64];
    __shared__ float s_ws2[64];
    __shared__ float s_red[128];
    __shared__ float s_num[KK][MM];
    __shared__ float s_den[KK];

    for (int i = t; i < 32*64; i += 128) s_ws1[i] = ws1[i];
    if (t < 64) { s_bs1[t] = bs1[t]; s_ws2[t] = ws2[t]; }
    for (int i = t; i < KK*MM; i += 128) ((float*)s_num)[i] = 0.f;
    if (t < KK) s_den[t] = 0.f;

    float gxr = gaze[b*2 + 0];
    float gyr = gaze[b*2 + 1];
    float gx = fminf(fmaxf(gxr * (WW - 1), 0.f), (float)(WW - 1));
    float gy = fminf(fmaxf(gyr * (HH - 1), 0.f), (float)(HH - 1));
    int x0 = (int)floorf(gx);
    int y0 = (int)floorf(gy);
    int rx0 = max(0, x0 - 5), ry0 = max(0, y0 - 5);
    int rx1 = min(WW - 1, x0 + 5), ry1 = min(HH - 1, y0 + 5);

    // gaussian weight for my neighbor
    int k = t;
    float gauss = 0.f;
    int xs = 0, ys = 0;
    if (k < KK) {
        int ox = (k % KS) - 5;
        int oy = (k / KS) - 5;
        xs = min(max(x0 + ox, 0), WW - 1);
        ys = min(max(y0 + oy, 0), HH - 1);
        float dx = (float)xs - gx;
        float dy = (float)ys - gy;
        // 2*sigma^2 = 2*(11/3)^2 = 242/9
        gauss = expf(-(dx*dx + dy*dy) * (9.0f / 242.0f));
    }
    s_red[t] = gauss;
    __syncthreads();
    for (int s = 64; s > 0; s >>= 1) {
        if (t < s) s_red[t] += s_red[t + s];
        __syncthreads();
    }
    float tot = fmaxf(s_red[0], 1e-8f);

    const float* cb = cell + (size_t)b * (MM*HWN);

    if (k < KK) {
        float gi[32];
        int idx = ys * WW + xs;
        #pragma unroll
        for (int m = 0; m < MM; m++) gi[m] = cb[m*HWN + idx];
        const float* wvp = WV + (size_t)b*WVDIM + k*MM;
        #pragma unroll
        for (int m = 0; m < MM; m++) gi[16 + m] = wvp[m];

        // strength MLP: relu(gi @ ws1 + bs1) -> dot ws2 + bs2 -> sigmoid
        float s = bs2[0];
        for (int j = 0; j < 64; j++) {
            float h = s_bs1[j];
            #pragma unroll
            for (int i = 0; i < 32; i++) h += gi[i] * s_ws1[i*64 + j];
            h = fmaxf(h, 0.f);
            s += h * s_ws2[j];
        }
        float gstr = 1.f / (1.f + expf(-s));
        float nw = gauss / tot;
        float w  = nw * gstr;

        int widx = (ys - ry0) * KS + (xs - rx0);
        atomicAdd(&s_den[widx], w);
        #pragma unroll
        for (int m = 0; m < MM; m++) {
            float nv = (1.f - w) * gi[m] + w * gi[16 + m];
            atomicAdd(&s_num[widx][m], w * nv);
        }
    }
    __syncthreads();

    // write updated = keep*cell + num
    float* ub = upd + (size_t)b * (MM*HWN);
    for (int e = t; e < MM*HWN; e += 128) {
        int m  = e >> 10;
        int hw = e & (HWN - 1);
        int y = hw >> 5, x = hw & 31;
        float v = cb[e];
        if (y >= ry0 && y <= ry1 && x >= rx0 && x <= rx1) {
            int widx = (y - ry0) * KS + (x - rx0);
            float keep = 1.f - fminf(s_den[widx], 1.f);
            v = keep * v + s_num[widx][m];
        }
        ub[e] = v;
    }
}

// ---------------- conv1: 16 -> 128 channels, 3x3 SAME ----------------
// grid (32, B): bx = rt*8 + ocb ; 16 oc per block, 8-row tile; 256 threads
__global__ void conv1_kernel(const float* __restrict__ upd,
                             const float* __restrict__ ck1,
                             const float* __restrict__ cb1,
                             float* __restrict__ Y1)
{
    int b  = blockIdx.y;
    int bx = blockIdx.x;
    int ocb = bx & 7;
    int rt  = bx >> 3;
    int oc_base = ocb * 16;
    int row0 = rt * 8;

    __shared__ float in_s[16][10][35];
    __shared__ float w_s[16][16][9];

    int t = threadIdx.x;
    const float* ub = upd + (size_t)b * (16*HWN);

    for (int idx = t; idx < 16*10*35; idx += 256) {
        int ic = idx / 350; int rem = idx - ic*350;
        int r = rem / 35;   int c = rem - r*35;
        int gr = row0 - 1 + r;
        int gc = c - 1;
        float v = 0.f;
        if (gr >= 0 && gr < HH && gc >= 0 && gc < WW)
            v = ub[ic*HWN + gr*WW + gc];
        in_s[ic][r][c] = v;
    }
    for (int idx = t; idx < 16*144; idx += 256) {
        int o = idx / 144; int rem = idx - o*144;
        ((float*)w_s)[o*144 + rem] = ck1[(size_t)(oc_base + o)*144 + rem];
    }
    __syncthreads();

    int oc_g = t >> 6;           // 0..3
    int pg = t & 63;
    int y = pg >> 3;             // 0..7
    int x = (pg & 7) * 4;        // 0..28
    int oc0 = oc_g * 4;

    float acc[4][4] = {};
    for (int ic = 0; ic < 16; ic++) {
        #pragma unroll
        for (int kh = 0; kh < 3; kh++) {
            float iv[6];
            #pragma unroll
            for (int i = 0; i < 6; i++) iv[i] = in_s[ic][y + kh][x + i];
            #pragma unroll
            for (int kw = 0; kw < 3; kw++) {
                float w0 = w_s[oc0+0][ic][kh*3+kw];
                float w1 = w_s[oc0+1][ic][kh*3+kw];
                float w2 = w_s[oc0+2][ic][kh*3+kw];
                float w3 = w_s[oc0+3][ic][kh*3+kw];
                #pragma unroll
                for (int i = 0; i < 4; i++) {
                    float v = iv[kw + i];
                    acc[0][i] += w0 * v;
                    acc[1][i] += w1 * v;
                    acc[2][i] += w2 * v;
                    acc[3][i] += w3 * v;
                }
            }
        }
    }
    float* yb = Y1 + (size_t)b * (128*HWN);
    #pragma unroll
    for (int j = 0; j < 4; j++) {
        int oc = oc_base + oc0 + j;
        float bias = cb1[oc];
        #pragma unroll
        for (int i = 0; i < 4; i++) {
            float v = fmaxf(acc[j][i] + bias, 0.f);
            yb[oc*HWN + (row0 + y)*WW + x + i] = v;
        }
    }
}

// ---------------- conv2: 128 -> 64 channels, 3x3 SAME ----------------
// grid (16, B): bx = tile*2 + ocb ; 32 oc per block, 16x8 px tile; 256 threads
__global__ void conv2_kernel(const float* __restrict__ Y1,
                             const float* __restrict__ ck2,
                             const float* __restrict__ cb2,
                             float* __restrict__ Y2)
{
    int b  = blockIdx.y;
    int bx = blockIdx.x;
    int ocb  = bx & 1;
    int tile = bx >> 1;          // 0..7
    int row0 = (tile >> 2) * 16; // 0 or 16
    int col0 = (tile & 3) * 8;   // 0,8,16,24
    int oc_base = ocb * 32;

    __shared__ float in_s[16][18][11];
    __shared__ float w_s[32][16][9];

    int t = threadIdx.x;
    int oc_g = t >> 5; int oc0 = oc_g * 4;   // warp-uniform
    int pg = t & 31;
    int y = pg >> 1;             // 0..15
    int x = (pg & 1) * 4;        // 0 or 4

    float acc[4][4] = {};
    const float* y1b = Y1 + (size_t)b * (128*HWN);

    for (int ch = 0; ch < 8; ch++) {
        __syncthreads();
        for (int idx = t; idx < 16*18*11; idx += 256) {
            int ic = idx / 198; int rem = idx - ic*198;
            int r = rem / 11;   int c = rem - r*11;
            int gr = row0 - 1 + r;
            int gc = col0 - 1 + c;
            float v = 0.f;
            if (gr >= 0 && gr < HH && gc >= 0 && gc < WW)
                v = y1b[(ch*16 + ic)*HWN + gr*WW + gc];
            in_s[ic][r][c] = v;
        }
        for (int idx = t; idx < 32*144; idx += 256) {
            int o = idx / 144; int rem = idx - o*144;
            ((float*)w_s)[o*144 + rem] =
                ck2[(size_t)(oc_base + o)*1152 + ch*144 + rem];
        }
        __syncthreads();

        for (int ic = 0; ic < 16; ic++) {
            #pragma unroll
            for (int kh = 0; kh < 3; kh++) {
                float iv[6];
                #pragma unroll
                for (int i = 0; i < 6; i++) iv[i] = in_s[ic][y + kh][x + i];
                #pragma unroll
                for (int kw = 0; kw < 3; kw++) {
                    float w0 = w_s[oc0+0][ic][kh*3+kw];
                    float w1 = w_s[oc0+1][ic][kh*3+kw];
                    float w2 = w_s[oc0+2][ic][kh*3+kw];
                    float w3 = w_s[oc0+3][ic][kh*3+kw];
                    #pragma unroll
                    for (int i = 0; i < 4; i++) {
                        float v = iv[kw + i];
                        acc[0][i] += w0 * v;
                        acc[1][i] += w1 * v;
                        acc[2][i] += w2 * v;
                        acc[3][i] += w3 * v;
                    }
                }
            }
        }
    }
    float* y2b = Y2 + (size_t)b * (64*HWN);
    #pragma unroll
    for (int j = 0; j < 4; j++) {
        int oc = oc_base + oc0 + j;
        float bias = cb2[oc];
        #pragma unroll
        for (int i = 0; i < 4; i++) {
            float v = fmaxf(acc[j][i] + bias, 0.f);
            y2b[oc*HWN + (row0 + y)*WW + col0 + x + i] = v;
        }
    }
}

// ---------------- adaptive avg pool 3x3 ----------------
__global__ void pool_kernel(const float* __restrict__ Y2, float* __restrict__ P)
{
    int gid = blockIdx.x * blockDim.x + threadIdx.x;
    if (gid >= BB * 576) return;
    int b = gid / 576;
    int r = gid - b * 576;
    int c = r / 9;
    int bin = r - c * 9;
    int bi = bin / 3, bj = bin - bi * 3;
    const int h0s[3] = {0, 10, 21};
    const int h1s[3] = {11, 22, 32};
    const float* base = Y2 + (size_t)b * (64*HWN) + c * HWN;
    float sum = 0.f;
    for (int h = h0s[bi]; h < h1s[bi]; h++)
        for (int w = h0s[bj]; w < h1s[bj]; w++)
            sum += base[h*WW + w];
    P[gid] = sum / (float)((h1s[bi]-h0s[bi]) * (h1s[bj]-h0s[bj]));
}

// ---------------- launch ----------------
extern "C" void kernel_launch(void* const* d_in, const int* in_sizes, int n_in,
                              void* d_out, int out_size)
{
    const float* features = (const float*)d_in[0];
    const float* cell     = (const float*)d_in[1];
    const float* gaze     = (const float*)d_in[2];
    const float* w1  = (const float*)d_in[3];
    const float* b1  = (const float*)d_in[4];
    const float* w2  = (const float*)d_in[5];
    const float* b2  = (const float*)d_in[6];
    const float* wv  = (const float*)d_in[7];
    const float* bv  = (const float*)d_in[8];
    const float* ws1 = (const float*)d_in[9];
    const float* bs1 = (const float*)d_in[10];
    const float* ws2 = (const float*)d_in[11];
    const float* bs2 = (const float*)d_in[12];
    const float* ck1 = (const float*)d_in[13];
    const float* cb1 = (const float*)d_in[14];
    const float* ck2 = (const float*)d_in[15];
    const float* cb2 = (const float*)d_in[16];
    const float* wo  = (const float*)d_in[17];
    const float* bo  = (const float*)d_in[18];

    float* out = (float*)d_out;                 // (B, 576)
    float* upd = out + (size_t)BB * 576;        // (B, 16, 32, 32)

    float *pX, *pC1, *pC2, *pWV, *pY1, *pY2, *pP;
    cudaGetSymbolAddress((void**)&pX,  g_X);
    cudaGetSymbolAddress((void**)&pC1, g_C1);
    cudaGetSymbolAddress((void**)&pC2, g_C2);
    cudaGetSymbolAddress((void**)&pWV, g_WV);
    cudaGetSymbolAddress((void**)&pY1, g_Y1);
    cudaGetSymbolAddress((void**)&pY2, g_Y2);
    cudaGetSymbolAddress((void**)&pP,  g_P);

    build_x_kernel<<<BB, XDIM>>>(features, gaze, pX);

    gemm_kernel<<<dim3(256/64, BB/64), 256>>>(pX,  w1, b1, pC1, BB, 256, XDIM, 1);
    gemm_kernel<<<dim3(128/64, BB/64), 256>>>(pC1, w2, b2, pC2, BB, 128, 256, 1);
    gemm_kernel<<<dim3((WVDIM+63)/64, BB/64), 256>>>(pC2, wv, bv, pWV, BB, WVDIM, 128, 0);

    scatter_kernel<<<BB, 128>>>(cell, gaze, pWV, ws1, bs1, ws2, bs2, upd);

    conv1_kernel<<<dim3(32, BB), 256>>>(upd, ck1, cb1, pY1);
    conv2_kernel<<<dim3(16, BB), 256>>>(pY1, ck2, cb2, pY2);

    pool_kernel<<<(BB*576 + 255)/256, 256>>>(pY2, pP);

    gemm_kernel<<<dim3(576/64, BB/64), 256>>>(pP, wo, bo, out, BB, 576, 576, 0);
}

// round 2
// speedup vs baseline: 1.4192x; 1.4192x over previous
#include <cuda_runtime.h>
#include <cstdint>

// ---------------- problem constants ----------------
#define BB 2048
#define FF 512
#define MM 16
#define HH 32
#define WW 32
#define PD 64
#define KS 11
#define KK (KS*KS)        // 121
#define HWN (HH*WW)       // 1024
#define XDIM (FF+PD)      // 576
#define WVDIM (KK*MM)     // 1936

// ---------------- scratch (device globals; allocation-free) ----------------
__device__ float g_X [(size_t)BB*XDIM];
__device__ float g_C1[(size_t)BB*256];
__device__ float g_C2[(size_t)BB*128];
__device__ float g_WV[(size_t)BB*WVDIM];
__device__ float g_Y1[(size_t)BB*128*HWN];     // 1.07 GB
__device__ float g_Y2[(size_t)BB*64*HWN];      // 537 MB
__device__ float g_P [(size_t)BB*576];

// ---------------- tf32 helpers ----------------
__device__ __forceinline__ float f2tf32(float x) {
    uint32_t r;
    asm("cvt.rna.tf32.f32 %0, %1;" : "=r"(r) : "f"(x));
    return __uint_as_float(r);
}

__device__ __forceinline__ void mma_tf32(float* d,
                                         uint32_t a0, uint32_t a1, uint32_t a2, uint32_t a3,
                                         uint32_t b0, uint32_t b1)
{
    asm volatile(
        "mma.sync.aligned.m16n8k8.row.col.f32.tf32.tf32.f32 "
        "{%0,%1,%2,%3},{%4,%5,%6,%7},{%8,%9},{%0,%1,%2,%3};"
        : "+f"(d[0]), "+f"(d[1]), "+f"(d[2]), "+f"(d[3])
        : "r"(a0), "r"(a1), "r"(a2), "r"(a3), "r"(b0), "r"(b1));
}

// ---------------- stage 0: build X = [features | pos_encoding] ----------------
__global__ void build_x_kernel(const float* __restrict__ feat,
                               const float* __restrict__ gaze,
                               float* __restrict__ X)
{
    int b = blockIdx.x;
    int t = threadIdx.x;  // 576 threads
    float v;
    if (t < FF) {
        v = feat[(size_t)b*FF + t];
    } else {
        int j = t - FF;
        int axis = j >> 5;
        int w = j & 31;
        int i = w >> 1;
        float p = gaze[b*2 + axis];
        float dv = expf(-(float)(2*i) * (9.210340371976184f / 32.0f));
        float a = p * dv;
        v = (w & 1) ? cosf(a) : sinf(a);
    }
    X[(size_t)b*XDIM + t] = v;
}

// ---------------- generic tiled GEMM (fp32) ----------------
__global__ void gemm_kernel(const float* __restrict__ A,
                            const float* __restrict__ W,
                            const float* __restrict__ bias,
                            float* __restrict__ C,
                            int Mdim, int Ndim, int Kdim, int relu)
{
    __shared__ float As[16][64];
    __shared__ float Bs[16][64];
    int bm0 = blockIdx.y * 64;
    int bn0 = blockIdx.x * 64;
    int t = threadIdx.x;
    int ty = t >> 4, tx = t & 15;
    float acc[4][4] = {};

    for (int k0 = 0; k0 < Kdim; k0 += 16) {
        {
            int m  = t >> 2;
            int kk = (t & 3) * 4;
            float4 a4 = *reinterpret_cast<const float4*>(&A[(size_t)(bm0 + m)*Kdim + k0 + kk]);
            As[kk+0][m] = a4.x; As[kk+1][m] = a4.y;
            As[kk+2][m] = a4.z; As[kk+3][m] = a4.w;
        }
        {
            int r = t >> 4;
            int c = (t & 15) * 4;
            int gn = bn0 + c;
            float4 b4;
            if (gn + 3 < Ndim) {
                b4 = *reinterpret_cast<const float4*>(&W[(size_t)(k0 + r)*Ndim + gn]);
            } else {
                b4.x = (gn+0 < Ndim) ? W[(size_t)(k0+r)*Ndim + gn+0] : 0.f;
                b4.y = (gn+1 < Ndim) ? W[(size_t)(k0+r)*Ndim + gn+1] : 0.f;
                b4.z = (gn+2 < Ndim) ? W[(size_t)(k0+r)*Ndim + gn+2] : 0.f;
                b4.w = (gn+3 < Ndim) ? W[(size_t)(k0+r)*Ndim + gn+3] : 0.f;
            }
            *reinterpret_cast<float4*>(&Bs[r][c]) = b4;
        }
        __syncthreads();
        #pragma unroll
        for (int kk = 0; kk < 16; kk++) {
            float4 a = *reinterpret_cast<const float4*>(&As[kk][ty*4]);
            float4 b = *reinterpret_cast<const float4*>(&Bs[kk][tx*4]);
            float av[4] = {a.x, a.y, a.z, a.w};
            float bv[4] = {b.x, b.y, b.z, b.w};
            #pragma unroll
            for (int j = 0; j < 4; j++)
                #pragma unroll
                for (int i = 0; i < 4; i++)
                    acc[j][i] += av[j] * bv[i];
        }
        __syncthreads();
    }
    #pragma unroll
    for (int j = 0; j < 4; j++) {
        int row = bm0 + ty*4 + j;
        #pragma unroll
        for (int i = 0; i < 4; i++) {
            int col = bn0 + tx*4 + i;
            if (col < Ndim) {
                float v = acc[j][i] + bias[col];
                if (relu) v = fmaxf(v, 0.f);
                C[(size_t)row*Ndim + col] = v;
            }
        }
    }
}

// ---------------- scatter/update stage (unchanged, passed exact) ----------------
__global__ void scatter_kernel(const float* __restrict__ cell,
                               const float* __restrict__ gaze,
                               const float* __restrict__ WV,
                               const float* __restrict__ ws1,
                               const float* __restrict__ bs1,
                               const float* __restrict__ ws2,
                               const float* __restrict__ bs2,
                               float* __restrict__ upd)
{
    int b = blockIdx.x;
    int t = threadIdx.x;

    __shared__ float s_ws1[32*64];
    __shared__ float s_bs1[64];
    __shared__ float s_ws2[64];
    __shared__ float s_red[128];
    __shared__ float s_num[KK][MM];
    __shared__ float s_den[KK];

    for (int i = t; i < 32*64; i += 128) s_ws1[i] = ws1[i];
    if (t < 64) { s_bs1[t] = bs1[t]; s_ws2[t] = ws2[t]; }
    for (int i = t; i < KK*MM; i += 128) ((float*)s_num)[i] = 0.f;
    if (t < KK) s_den[t] = 0.f;

    float gxr = gaze[b*2 + 0];
    float gyr = gaze[b*2 + 1];
    float gx = fminf(fmaxf(gxr * (WW - 1), 0.f), (float)(WW - 1));
    float gy = fminf(fmaxf(gyr * (HH - 1), 0.f), (float)(HH - 1));
    int x0 = (int)floorf(gx);
    int y0 = (int)floorf(gy);
    int rx0 = max(0, x0 - 5), ry0 = max(0, y0 - 5);
    int rx1 = min(WW - 1, x0 + 5), ry1 = min(HH - 1, y0 + 5);

    int k = t;
    float gauss = 0.f;
    int xs = 0, ys = 0;
    if (k < KK) {
        int ox = (k % KS) - 5;
        int oy = (k / KS) - 5;
        xs = min(max(x0 + ox, 0), WW - 1);
        ys = min(max(y0 + oy, 0), HH - 1);
        float dx = (float)xs - gx;
        float dy = (float)ys - gy;
        gauss = expf(-(dx*dx + dy*dy) * (9.0f / 242.0f));
    }
    s_red[t] = gauss;
    __syncthreads();
    for (int s = 64; s > 0; s >>= 1) {
        if (t < s) s_red[t] += s_red[t + s];
        __syncthreads();
    }
    float tot = fmaxf(s_red[0], 1e-8f);

    const float* cb = cell + (size_t)b * (MM*HWN);

    if (k < KK) {
        float gi[32];
        int idx = ys * WW + xs;
        #pragma unroll
        for (int m = 0; m < MM; m++) gi[m] = cb[m*HWN + idx];
        const float* wvp = WV + (size_t)b*WVDIM + k*MM;
        #pragma unroll
        for (int m = 0; m < MM; m++) gi[16 + m] = wvp[m];

        float s = bs2[0];
        for (int j = 0; j < 64; j++) {
            float h = s_bs1[j];
            #pragma unroll
            for (int i = 0; i < 32; i++) h += gi[i] * s_ws1[i*64 + j];
            h = fmaxf(h, 0.f);
            s += h * s_ws2[j];
        }
        float gstr = 1.f / (1.f + expf(-s));
        float nw = gauss / tot;
        float w  = nw * gstr;

        int widx = (ys - ry0) * KS + (xs - rx0);
        atomicAdd(&s_den[widx], w);
        #pragma unroll
        for (int m = 0; m < MM; m++) {
            float nv = (1.f - w) * gi[m] + w * gi[16 + m];
            atomicAdd(&s_num[widx][m], w * nv);
        }
    }
    __syncthreads();

    float* ub = upd + (size_t)b * (MM*HWN);
    for (int e = t; e < MM*HWN; e += 128) {
        int m  = e >> 10;
        int hw = e & (HWN - 1);
        int y = hw >> 5, x = hw & 31;
        float v = cb[e];
        if (y >= ry0 && y <= ry1 && x >= rx0 && x <= rx1) {
            int widx = (y - ry0) * KS + (x - rx0);
            float keep = 1.f - fminf(s_den[widx], 1.f);
            v = keep * v + s_num[widx][m];
        }
        ub[e] = v;
    }
}

// ---------------- conv1 (16 -> 128 ch, 3x3 SAME) via tf32 mma ----------------
// grid (8, B): 4-row tile; 512 threads = 16 warps
// warp: mtile = w&7 (16 oc of 128), half = w>>3 (64 px of 128). acc 8 ntiles x 4.
__global__ __launch_bounds__(512)
void conv1_mma_kernel(const float* __restrict__ upd,
                      const float* __restrict__ ck1,
                      const float* __restrict__ cb1,
                      float* __restrict__ Y1)
{
    __shared__ float in_s[16][6][36];   // [ic][yy 0..5][xx 0..33], rows row0-1..row0+4
    __shared__ float w_s[16][128];      // [ic][oc] for current tap

    int b = blockIdx.y;
    int row0 = blockIdx.x * 4;
    int t = threadIdx.x;
    int w = t >> 5, lane = t & 31;
    int g = lane >> 2, tg = lane & 3;
    int mt = w & 7, half = w >> 3;
    int oc0 = mt * 16;

    const float* src = upd + (size_t)b * (16*HWN);

    // stage input tile once (tf32-rounded)
    for (int i = t; i < 16*6*34; i += 512) {
        int ic = i / 204; int rem = i - ic*204;
        int yy = rem / 34; int xx = rem - yy*34;
        int gr = row0 - 1 + yy;
        int gc = xx - 1;
        float v = 0.f;
        if (gr >= 0 && gr < HH && gc >= 0 && gc < WW)
            v = src[ic*HWN + gr*WW + gc];
        in_s[ic][yy][xx] = f2tf32(v);
    }

    float acc[8][4] = {};

    for (int tap = 0; tap < 9; tap++) {
        __syncthreads();   // protects w_s reuse (and input on first iter)
        for (int i = t; i < 16*128; i += 512) {
            int ic = i >> 7; int oc = i & 127;
            w_s[ic][oc] = f2tf32(ck1[(size_t)oc*144 + ic*9 + tap]);
        }
        __syncthreads();
        int kh = tap / 3, kw = tap - kh*3;

        #pragma unroll
        for (int kc = 0; kc < 2; kc++) {
            uint32_t a0 = __float_as_uint(w_s[kc*8 + tg    ][oc0 + g    ]);
            uint32_t a1 = __float_as_uint(w_s[kc*8 + tg    ][oc0 + g + 8]);
            uint32_t a2 = __float_as_uint(w_s[kc*8 + tg + 4][oc0 + g    ]);
            uint32_t a3 = __float_as_uint(w_s[kc*8 + tg + 4][oc0 + g + 8]);
            #pragma unroll
            for (int nt = 0; nt < 8; nt++) {
                int yy = half*2 + (nt >> 2) + kh;
                int xx = (nt & 3)*8 + g + kw;
                uint32_t b0 = __float_as_uint(in_s[kc*8 + tg    ][yy][xx]);
                uint32_t b1 = __float_as_uint(in_s[kc*8 + tg + 4][yy][xx]);
                mma_tf32(acc[nt], a0, a1, a2, a3, b0, b1);
            }
        }
    }

    float* dst = Y1 + (size_t)b * (128*HWN);
    float bias_lo = cb1[oc0 + g];
    float bias_hi = cb1[oc0 + g + 8];
    #pragma unroll
    for (int nt = 0; nt < 8; nt++) {
        int y = row0 + half*2 + (nt >> 2);
        int x = (nt & 3)*8 + 2*tg;
        float2 vlo = { fmaxf(acc[nt][0] + bias_lo, 0.f), fmaxf(acc[nt][1] + bias_lo, 0.f) };
        float2 vhi = { fmaxf(acc[nt][2] + bias_hi, 0.f), fmaxf(acc[nt][3] + bias_hi, 0.f) };
        *reinterpret_cast<float2*>(&dst[(oc0 + g    )*HWN + y*WW + x]) = vlo;
        *reinterpret_cast<float2*>(&dst[(oc0 + g + 8)*HWN + y*WW + x]) = vhi;
    }
}

// ---------------- conv2 (128 -> 64 ch, 3x3 SAME) via tf32 mma ----------------
// grid (4, B): 8-row tile; 512 threads = 16 warps
// warp: mtile = w&3 (16 oc of 64), quarter = w>>2 (64 px of 256). acc 8 ntiles x 4.
__global__ __launch_bounds__(512)
void conv2_mma_kernel(const float* __restrict__ Y1,
                      const float* __restrict__ ck2,
                      const float* __restrict__ cb2,
                      float* __restrict__ Y2)
{
    __shared__ float in_s[8][10][36];   // [icl][yy 0..9][xx 0..33]
    __shared__ float w_s[9][8][64];     // [tap][icl][oc]

    int b = blockIdx.y;
    int row0 = blockIdx.x * 8;
    int t = threadIdx.x;
    int w = t >> 5, lane = t & 31;
    int g = lane >> 2, tg = lane & 3;
    int mt = w & 3, q = w >> 2;
    int oc0 = mt * 16;

    const float* src = Y1 + (size_t)b * (128*HWN);
    float acc[8][4] = {};

    for (int c8 = 0; c8 < 16; c8++) {
        __syncthreads();
        // stage input chunk (8 ic, 10 rows, 34 cols)
        for (int i = t; i < 8*10*34; i += 512) {
            int ic = i / 340; int rem = i - ic*340;
            int yy = rem / 34; int xx = rem - yy*34;
            int gr = row0 - 1 + yy;
            int gc = xx - 1;
            float v = 0.f;
            if (gr >= 0 && gr < HH && gc >= 0 && gc < WW)
                v = src[(c8*8 + ic)*HWN + gr*WW + gc];
            in_s[ic][yy][xx] = f2tf32(v);
        }
        // stage weight chunk (9 taps, 8 ic, 64 oc)
        for (int i = t; i < 9*8*64; i += 512) {
            int tap = i / 512; int rem = i - tap*512;
            int ic = rem >> 6; int oc = rem & 63;
            w_s[tap][ic][oc] = f2tf32(ck2[(size_t)oc*1152 + (c8*8 + ic)*9 + tap]);
        }
        __syncthreads();

        #pragma unroll
        for (int tap = 0; tap < 9; tap++) {
            int kh = tap / 3, kw = tap - kh*3;
            uint32_t a0 = __float_as_uint(w_s[tap][tg    ][oc0 + g    ]);
            uint32_t a1 = __float_as_uint(w_s[tap][tg    ][oc0 + g + 8]);
            uint32_t a2 = __float_as_uint(w_s[tap][tg + 4][oc0 + g    ]);
            uint32_t a3 = __float_as_uint(w_s[tap][tg + 4][oc0 + g + 8]);
            #pragma unroll
            for (int nt = 0; nt < 8; nt++) {
                int yy = q*2 + (nt >> 2) + kh;
                int xx = (nt & 3)*8 + g + kw;
                uint32_t b0 = __float_as_uint(in_s[tg    ][yy][xx]);
                uint32_t b1 = __float_as_uint(in_s[tg + 4][yy][xx]);
                mma_tf32(acc[nt], a0, a1, a2, a3, b0, b1);
            }
        }
    }

    float* dst = Y2 + (size_t)b * (64*HWN);
    float bias_lo = cb2[oc0 + g];
    float bias_hi = cb2[oc0 + g + 8];
    #pragma unroll
    for (int nt = 0; nt < 8; nt++) {
        int y = row0 + q*2 + (nt >> 2);
        int x = (nt & 3)*8 + 2*tg;
        float2 vlo = { fmaxf(acc[nt][0] + bias_lo, 0.f), fmaxf(acc[nt][1] + bias_lo, 0.f) };
        float2 vhi = { fmaxf(acc[nt][2] + bias_hi, 0.f), fmaxf(acc[nt][3] + bias_hi, 0.f) };
        *reinterpret_cast<float2*>(&dst[(oc0 + g    )*HWN + y*WW + x]) = vlo;
        *reinterpret_cast<float2*>(&dst[(oc0 + g + 8)*HWN + y*WW + x]) = vhi;
    }
}

// ---------------- adaptive avg pool 3x3 ----------------
__global__ void pool_kernel(const float* __restrict__ Y2, float* __restrict__ P)
{
    int gid = blockIdx.x * blockDim.x + threadIdx.x;
    if (gid >= BB * 576) return;
    int b = gid / 576;
    int r = gid - b * 576;
    int c = r / 9;
    int bin = r - c * 9;
    int bi = bin / 3, bj = bin - bi * 3;
    const int h0s[3] = {0, 10, 21};
    const int h1s[3] = {11, 22, 32};
    const float* base = Y2 + (size_t)b * (64*HWN) + c * HWN;
    float sum = 0.f;
    for (int h = h0s[bi]; h < h1s[bi]; h++)
        for (int w = h0s[bj]; w < h1s[bj]; w++)
            sum += base[h*WW + w];
    P[gid] = sum / (float)((h1s[bi]-h0s[bi]) * (h1s[bj]-h0s[bj]));
}

// ---------------- launch ----------------
extern "C" void kernel_launch(void* const* d_in, const int* in_sizes, int n_in,
                              void* d_out, int out_size)
{
    const float* features = (const float*)d_in[0];
    const float* cell     = (const float*)d_in[1];
    const float* gaze     = (const float*)d_in[2];
    const float* w1  = (const float*)d_in[3];
    const float* b1  = (const float*)d_in[4];
    const float* w2  = (const float*)d_in[5];
    const float* b2  = (const float*)d_in[6];
    const float* wv  = (const float*)d_in[7];
    const float* bv  = (const float*)d_in[8];
    const float* ws1 = (const float*)d_in[9];
    const float* bs1 = (const float*)d_in[10];
    const float* ws2 = (const float*)d_in[11];
    const float* bs2 = (const float*)d_in[12];
    const float* ck1 = (const float*)d_in[13];
    const float* cb1 = (const float*)d_in[14];
    const float* ck2 = (const float*)d_in[15];
    const float* cb2 = (const float*)d_in[16];
    const float* wo  = (const float*)d_in[17];
    const float* bo  = (const float*)d_in[18];

    float* out = (float*)d_out;                 // (B, 576)
    float* upd = out + (size_t)BB * 576;        // (B, 16, 32, 32)

    float *pX, *pC1, *pC2, *pWV, *pY1, *pY2, *pP;
    cudaGetSymbolAddress((void**)&pX,  g_X);
    cudaGetSymbolAddress((void**)&pC1, g_C1);
    cudaGetSymbolAddress((void**)&pC2, g_C2);
    cudaGetSymbolAddress((void**)&pWV, g_WV);
    cudaGetSymbolAddress((void**)&pY1, g_Y1);
    cudaGetSymbolAddress((void**)&pY2, g_Y2);
    cudaGetSymbolAddress((void**)&pP,  g_P);

    build_x_kernel<<<BB, XDIM>>>(features, gaze, pX);

    gemm_kernel<<<dim3(256/64, BB/64), 256>>>(pX,  w1, b1, pC1, BB, 256, XDIM, 1);
    gemm_kernel<<<dim3(128/64, BB/64), 256>>>(pC1, w2, b2, pC2, BB, 128, 256, 1);
    gemm_kernel<<<dim3((WVDIM+63)/64, BB/64), 256>>>(pC2, wv, bv, pWV, BB, WVDIM, 128, 0);

    scatter_kernel<<<BB, 128>>>(cell, gaze, pWV, ws1, bs1, ws2, bs2, upd);

    conv1_mma_kernel<<<dim3(8, BB), 512>>>(upd, ck1, cb1, pY1);
    conv2_mma_kernel<<<dim3(4, BB), 512>>>(pY1, ck2, cb2, pY2);

    pool_kernel<<<(BB*576 + 255)/256, 256>>>(pY2, pP);

    gemm_kernel<<<dim3(576/64, BB/64), 256>>>(pP, wo, bo, out, BB, 576, 576, 0);
}

// round 8
// speedup vs baseline: 5.7799x; 4.0727x over previous
#include <cuda_runtime.h>
#include <cuda_fp16.h>
#include <cstdint>

#define BB 2048
#define FF 512
#define MM 16
#define HH 32
#define WW 32
#define PD 64
#define KS 11
#define KK (KS*KS)
#define HWN (HH*WW)
#define XDIM (FF+PD)
#define WVDIM (KK*MM)

// ---------------- scratch (device globals; allocation-free) ----------------
__device__ float  g_X [(size_t)BB*XDIM];
__device__ float  g_C1[(size_t)BB*256];
__device__ float  g_C2[(size_t)BB*128];
__device__ float  g_WV[(size_t)BB*WVDIM];
__device__ __align__(16) __half g_updh[(size_t)BB*HWN*16];    // pixel-major [b][px][ic]
__device__ __align__(16) __half g_Y1h [(size_t)BB*HWN*128];   // pixel-major [b][px][oc]
__device__ float  g_Y2[(size_t)BB*64*HWN];                    // channel-major
__device__ float  g_P [(size_t)BB*576];
__device__ __align__(16) __half g_W1h[1152*16];               // conv1 w: rows tap*128+oc, swizzled
__device__ __align__(16) __half g_W2h[8*576*16];              // conv2 w: [chunk][tap*64+oc], swizzled

// ---------------- fp16 mma m16n8k16 ----------------
__device__ __forceinline__ void mma16816(float* d, const uint32_t* a,
                                         uint32_t b0, uint32_t b1)
{
    asm volatile(
        "mma.sync.aligned.m16n8k16.row.col.f32.f16.f16.f32 "
        "{%0,%1,%2,%3},{%4,%5,%6,%7},{%8,%9},{%0,%1,%2,%3};"
        : "+f"(d[0]), "+f"(d[1]), "+f"(d[2]), "+f"(d[3])
        : "r"(a[0]), "r"(a[1]), "r"(a[2]), "r"(a[3]), "r"(b0), "r"(b1));
}

// ---------------- weight prep (fp16, 16B-half swizzle by row bit2) ----------------
__global__ void prep_w1_kernel(const float* __restrict__ ck1) {
    int i = blockIdx.x * blockDim.x + threadIdx.x;
    if (i >= 9*128*16) return;
    int ic = i & 15, r = i >> 4;            // r = tap*128 + oc
    int tap = r >> 7, oc = r & 127;
    float v = ck1[(size_t)oc*144 + ic*9 + tap];
    uint32_t byte = (uint32_t)r*32 + ((((ic>>3) ^ (r>>2)) & 1) << 4) + (ic & 7)*2;
    g_W1h[byte >> 1] = __float2half(v);
}
__global__ void prep_w2_kernel(const float* __restrict__ ck2) {
    int i = blockIdx.x * blockDim.x + threadIdx.x;
    if (i >= 8*576*16) return;
    int il = i & 15, rg = i >> 4;           // rg = c*576 + rs, rs = tap*64 + oc
    int c = rg / 576, rs = rg - c*576;
    int tap = rs >> 6, oc = rs & 63;
    int ic = c*16 + il;
    float v = ck2[(size_t)oc*1152 + ic*9 + tap];
    uint32_t byte = (uint32_t)rg*32 + ((((il>>3) ^ (rs>>2)) & 1) << 4) + (il & 7)*2;
    g_W2h[byte >> 1] = __float2half(v);
}

// ---------------- stage 0: build X ----------------
__global__ void build_x_kernel(const float* __restrict__ feat,
                               const float* __restrict__ gaze,
                               float* __restrict__ X)
{
    int b = blockIdx.x, t = threadIdx.x;
    float v;
    if (t < FF) v = feat[(size_t)b*FF + t];
    else {
        int j = t - FF, axis = j >> 5, w = j & 31, i = w >> 1;
        float p = gaze[b*2 + axis];
        float dv = expf(-(float)(2*i) * (9.210340371976184f / 32.0f));
        float a = p * dv;
        v = (w & 1) ? cosf(a) : sinf(a);
    }
    X[(size_t)b*XDIM + t] = v;
}

// ---------------- fp32 GEMM (MLP heads; passed exact) ----------------
__global__ void gemm_kernel(const float* __restrict__ A, const float* __restrict__ W,
                            const float* __restrict__ bias, float* __restrict__ C,
                            int Mdim, int Ndim, int Kdim, int relu)
{
    __shared__ float As[16][64];
    __shared__ float Bs[16][64];
    int bm0 = blockIdx.y * 64, bn0 = blockIdx.x * 64;
    int t = threadIdx.x, ty = t >> 4, tx = t & 15;
    float acc[4][4] = {};
    for (int k0 = 0; k0 < Kdim; k0 += 16) {
        { int m = t >> 2, kk = (t & 3) * 4;
          float4 a4 = *reinterpret_cast<const float4*>(&A[(size_t)(bm0 + m)*Kdim + k0 + kk]);
          As[kk+0][m] = a4.x; As[kk+1][m] = a4.y; As[kk+2][m] = a4.z; As[kk+3][m] = a4.w; }
        { int r = t >> 4, c = (t & 15) * 4, gn = bn0 + c;
          float4 b4;
          if (gn + 3 < Ndim) b4 = *reinterpret_cast<const float4*>(&W[(size_t)(k0 + r)*Ndim + gn]);
          else {
              b4.x = (gn+0 < Ndim) ? W[(size_t)(k0+r)*Ndim + gn+0] : 0.f;
              b4.y = (gn+1 < Ndim) ? W[(size_t)(k0+r)*Ndim + gn+1] : 0.f;
              b4.z = (gn+2 < Ndim) ? W[(size_t)(k0+r)*Ndim + gn+2] : 0.f;
              b4.w = (gn+3 < Ndim) ? W[(size_t)(k0+r)*Ndim + gn+3] : 0.f;
          }
          *reinterpret_cast<float4*>(&Bs[r][c]) = b4; }
        __syncthreads();
        #pragma unroll
        for (int kk = 0; kk < 16; kk++) {
            float4 a = *reinterpret_cast<const float4*>(&As[kk][ty*4]);
            float4 b = *reinterpret_cast<const float4*>(&Bs[kk][tx*4]);
            float av[4] = {a.x,a.y,a.z,a.w}, bv[4] = {b.x,b.y,b.z,b.w};
            #pragma unroll
            for (int j = 0; j < 4; j++)
                #pragma unroll
                for (int i = 0; i < 4; i++) acc[j][i] += av[j] * bv[i];
        }
        __syncthreads();
    }
    #pragma unroll
    for (int j = 0; j < 4; j++) {
        int row = bm0 + ty*4 + j;
        #pragma unroll
        for (int i = 0; i < 4; i++) {
            int col = bn0 + tx*4 + i;
            if (col < Ndim) {
                float v = acc[j][i] + bias[col];
                if (relu) v = fmaxf(v, 0.f);
                C[(size_t)row*Ndim + col] = v;
            }
        }
    }
}

// ---------------- scatter/update (exact) + fp16 pixel-major copy ----------------
__global__ void scatter_kernel(const float* __restrict__ cell, const float* __restrict__ gaze,
                               const float* __restrict__ WV,
                               const float* __restrict__ ws1, const float* __restrict__ bs1,
                               const float* __restrict__ ws2, const float* __restrict__ bs2,
                               float* __restrict__ upd, __half* __restrict__ updh)
{
    int b = blockIdx.x, t = threadIdx.x;
    __shared__ float s_ws1[32*64];
    __shared__ float s_bs1[64];
    __shared__ float s_ws2[64];
    __shared__ float s_red[128];
    __shared__ float s_num[KK][MM];
    __shared__ float s_den[KK];

    for (int i = t; i < 32*64; i += 128) s_ws1[i] = ws1[i];
    if (t < 64) { s_bs1[t] = bs1[t]; s_ws2[t] = ws2[t]; }
    for (int i = t; i < KK*MM; i += 128) ((float*)s_num)[i] = 0.f;
    if (t < KK) s_den[t] = 0.f;

    float gx = fminf(fmaxf(gaze[b*2+0] * (WW-1), 0.f), (float)(WW-1));
    float gy = fminf(fmaxf(gaze[b*2+1] * (HH-1), 0.f), (float)(HH-1));
    int x0 = (int)floorf(gx), y0 = (int)floorf(gy);
    int rx0 = max(0, x0-5), ry0 = max(0, y0-5);
    int rx1 = min(WW-1, x0+5), ry1 = min(HH-1, y0+5);

    int k = t;
    float gauss = 0.f;
    int xs = 0, ys = 0;
    if (k < KK) {
        int ox = (k % KS) - 5, oy = (k / KS) - 5;
        xs = min(max(x0 + ox, 0), WW-1);
        ys = min(max(y0 + oy, 0), HH-1);
        float dx = (float)xs - gx, dy = (float)ys - gy;
        gauss = expf(-(dx*dx + dy*dy) * (9.0f / 242.0f));
    }
    s_red[t] = gauss;
    __syncthreads();
    for (int s = 64; s > 0; s >>= 1) { if (t < s) s_red[t] += s_red[t+s]; __syncthreads(); }
    float tot = fmaxf(s_red[0], 1e-8f);

    const float* cb = cell + (size_t)b * (MM*HWN);
    if (k < KK) {
        float gi[32];
        int idx = ys * WW + xs;
        #pragma unroll
        for (int m = 0; m < MM; m++) gi[m] = cb[m*HWN + idx];
        const float* wvp = WV + (size_t)b*WVDIM + k*MM;
        #pragma unroll
        for (int m = 0; m < MM; m++) gi[16+m] = wvp[m];
        float s = bs2[0];
        for (int j = 0; j < 64; j++) {
            float h = s_bs1[j];
            #pragma unroll
            for (int i = 0; i < 32; i++) h += gi[i] * s_ws1[i*64 + j];
            s += fmaxf(h, 0.f) * s_ws2[j];
        }
        float w = (gauss / tot) * (1.f / (1.f + expf(-s)));
        int widx = (ys - ry0) * KS + (xs - rx0);
        atomicAdd(&s_den[widx], w);
        #pragma unroll
        for (int m = 0; m < MM; m++)
            atomicAdd(&s_num[widx][m], w * ((1.f - w) * gi[m] + w * gi[16+m]));
    }
    __syncthreads();

    float* ub = upd + (size_t)b * (MM*HWN);
    __half* uh = updh + ((size_t)b << 14);
    for (int e = t; e < MM*HWN; e += 128) {
        int m = e >> 10, hw = e & (HWN-1);
        int y = hw >> 5, x = hw & 31;
        float v = cb[e];
        if (y >= ry0 && y <= ry1 && x >= rx0 && x <= rx1) {
            int widx = (y - ry0) * KS + (x - rx0);
            v = (1.f - fminf(s_den[widx], 1.f)) * v + s_num[widx][m];
        }
        ub[e] = v;
        uh[hw*16 + m] = __float2half(v);
    }
}

// ---------------- conv1: 16->128 ch, fp16 mma, m=px n=oc, K=144 ----------------
// grid (4, B); 512 thr = 16 warps: wp=w&7 -> px0, och=w>>3 -> oc0 (0/64)
__global__ __launch_bounds__(512)
void conv1_hmma(const __half* __restrict__ updh, const __half* __restrict__ W1,
                const float* __restrict__ cb1, __half* __restrict__ Y1h)
{
    __shared__ __align__(16) char sA[340*32];    // ext tile [e=ey*34+ex][16 ic], swizzled
    __shared__ __align__(16) char sW[1152*32];   // rows tap*128+oc, swizzled

    int b = blockIdx.y, tile = blockIdx.x;
    int row0 = tile*8;
    int tid = threadIdx.x, w = tid >> 5, lane = tid & 31;
    int g = lane >> 2, t4 = (lane & 3)*4;
    int px0 = (w & 7)*32, oc0 = (w >> 3)*64;

    { const uint4* src = (const uint4*)W1;
      uint4* dst = (uint4*)sW;
      for (int i = tid; i < 2304; i += 512) dst[i] = src[i]; }

    const __half* ub = updh + ((size_t)b << 14);
    for (int i = tid; i < 680; i += 512) {
        int e = i >> 1, h = i & 1;
        int ey = e / 34, ex = e - ey*34;
        int y = row0 - 1 + ey, x = ex - 1;
        uint4 v = make_uint4(0,0,0,0);
        if (y >= 0 && y < 32 && x >= 0 && x < 32)
            v = *(const uint4*)(ub + ((y << 5) + x)*16 + h*8);
        *(uint4*)(sA + e*32 + (((h ^ (e >> 2)) & 1) << 4)) = v;
    }
    __syncthreads();

    float acc[2][8][4] = {};
    #pragma unroll
    for (int tap = 0; tap < 9; tap++) {
        int dy = tap/3 - 1, dx = tap%3 - 1;
        uint32_t A[2][4];
        #pragma unroll
        for (int mt = 0; mt < 2; mt++) {
            int p = px0 + mt*16 + g;
            int e = ((p >> 5) + 1 + dy)*34 + (p & 31) + 1 + dx;
            int e8 = e + 8;   // p and p+8 share the image row; x+dx+8 <= 33
            A[mt][0] = *(const uint32_t*)(sA + e *32 + (((e  >> 2) & 1) << 4) + t4);
            A[mt][1] = *(const uint32_t*)(sA + e8*32 + (((e8 >> 2) & 1) << 4) + t4);
            A[mt][2] = *(const uint32_t*)(sA + e *32 + ((((e  >> 2) ^ 1) & 1) << 4) + t4);
            A[mt][3] = *(const uint32_t*)(sA + e8*32 + ((((e8 >> 2) ^ 1) & 1) << 4) + t4);
        }
        #pragma unroll
        for (int nt = 0; nt < 8; nt++) {
            int rs = tap*128 + oc0 + nt*8 + g;
            uint32_t b0 = *(const uint32_t*)(sW + rs*32 + (((rs >> 2) & 1) << 4) + t4);
            uint32_t b1 = *(const uint32_t*)(sW + rs*32 + ((((rs >> 2) ^ 1) & 1) << 4) + t4);
            mma16816(acc[0][nt], A[0], b0, b1);
            mma16816(acc[1][nt], A[1], b0, b1);
        }
    }

    __half* dst = Y1h + ((size_t)b << 17);
    #pragma unroll
    for (int nt = 0; nt < 8; nt++) {
        int oc = oc0 + nt*8 + (t4 >> 1);
        float bf0 = cb1[oc], bf1 = cb1[oc + 1];
        #pragma unroll
        for (int mt = 0; mt < 2; mt++) {
            int gpx = tile*256 + px0 + mt*16 + g;
            float v0 = fmaxf(acc[mt][nt][0] + bf0, 0.f);
            float v1 = fmaxf(acc[mt][nt][1] + bf1, 0.f);
            float v2 = fmaxf(acc[mt][nt][2] + bf0, 0.f);
            float v3 = fmaxf(acc[mt][nt][3] + bf1, 0.f);
            *(__half2*)(dst + (size_t)gpx*128 + oc)       = __floats2half2_rn(v0, v1);
            *(__half2*)(dst + (size_t)(gpx + 8)*128 + oc) = __floats2half2_rn(v2, v3);
        }
    }
}

// ---------------- conv2: 128->64 ch, fp16 mma, m=px n=oc, K=1152 (8 chunks) ----------------
// grid (4, B); 256 thr = 8 warps, each 32px x 64oc
__global__ __launch_bounds__(256, 2)
void conv2_hmma(const __half* __restrict__ Y1h, const __half* __restrict__ W2,
                const float* __restrict__ cb2, float* __restrict__ Y2)
{
    __shared__ __align__(16) char sA[340*32];
    __shared__ __align__(16) char sW[576*32];

    int b = blockIdx.y, tile = blockIdx.x;
    int row0 = tile*8;
    int tid = threadIdx.x, w = tid >> 5, lane = tid & 31;
    int g = lane >> 2, t4 = (lane & 3)*4;
    int px0 = w*32;

    const __half* yb = Y1h + ((size_t)b << 17);
    float acc[2][8][4] = {};

    for (int c = 0; c < 8; c++) {
        if (c) __syncthreads();
        for (int i = tid; i < 680; i += 256) {
            int e = i >> 1, h = i & 1;
            int ey = e / 34, ex = e - ey*34;
            int y = row0 - 1 + ey, x = ex - 1;
            uint4 v = make_uint4(0,0,0,0);
            if (y >= 0 && y < 32 && x >= 0 && x < 32)
                v = *(const uint4*)(yb + ((y << 5) + x)*128 + c*16 + h*8);
            *(uint4*)(sA + e*32 + (((h ^ (e >> 2)) & 1) << 4)) = v;
        }
        { const uint4* src = (const uint4*)W2 + c*1152;
          uint4* dst = (uint4*)sW;
          for (int i = tid; i < 1152; i += 256) dst[i] = src[i]; }
        __syncthreads();

        #pragma unroll
        for (int tap = 0; tap < 9; tap++) {
            int dy = tap/3 - 1, dx = tap%3 - 1;
            uint32_t A[2][4];
            #pragma unroll
            for (int mt = 0; mt < 2; mt++) {
                int p = px0 + mt*16 + g;
                int e = ((p >> 5) + 1 + dy)*34 + (p & 31) + 1 + dx;
                int e8 = e + 8;
                A[mt][0] = *(const uint32_t*)(sA + e *32 + (((e  >> 2) & 1) << 4) + t4);
                A[mt][1] = *(const uint32_t*)(sA + e8*32 + (((e8 >> 2) & 1) << 4) + t4);
                A[mt][2] = *(const uint32_t*)(sA + e *32 + ((((e  >> 2) ^ 1) & 1) << 4) + t4);
                A[mt][3] = *(const uint32_t*)(sA + e8*32 + ((((e8 >> 2) ^ 1) & 1) << 4) + t4);
            }
            #pragma unroll
            for (int nt = 0; nt < 8; nt++) {
                int rs = tap*64 + nt*8 + g;
                uint32_t b0 = *(const uint32_t*)(sW + rs*32 + (((rs >> 2) & 1) << 4) + t4);
                uint32_t b1 = *(const uint32_t*)(sW + rs*32 + ((((rs >> 2) ^ 1) & 1) << 4) + t4);
                mma16816(acc[0][nt], A[0], b0, b1);
                mma16816(acc[1][nt], A[1], b0, b1);
            }
        }
    }

    float* dst = Y2 + ((size_t)b << 16);
    #pragma unroll
    for (int nt = 0; nt < 8; nt++) {
        int oc = nt*8 + (t4 >> 1);
        float bf0 = cb2[oc], bf1 = cb2[oc + 1];
        #pragma unroll
        for (int mt = 0; mt < 2; mt++) {
            int gpx = tile*256 + px0 + mt*16 + g;
            dst[(size_t)oc*HWN + gpx]           = fmaxf(acc[mt][nt][0] + bf0, 0.f);
            dst[(size_t)(oc+1)*HWN + gpx]       = fmaxf(acc[mt][nt][1] + bf1, 0.f);
            dst[(size_t)oc*HWN + gpx + 8]       = fmaxf(acc[mt][nt][2] + bf0, 0.f);
            dst[(size_t)(oc+1)*HWN + gpx + 8]   = fmaxf(acc[mt][nt][3] + bf1, 0.f);
        }
    }
}

// ---------------- adaptive avg pool 3x3 ----------------
__global__ void pool_kernel(const float* __restrict__ Y2, float* __restrict__ P)
{
    int gid = blockIdx.x * blockDim.x + threadIdx.x;
    if (gid >= BB * 576) return;
    int b = gid / 576, r = gid - b*576;
    int c = r / 9, bin = r - c*9, bi = bin / 3, bj = bin - bi*3;
    const int h0s[3] = {0, 10, 21};
    const int h1s[3] = {11, 22, 32};
    const float* base = Y2 + (size_t)b * (64*HWN) + c * HWN;
    float sum = 0.f;
    for (int h = h0s[bi]; h < h1s[bi]; h++)
        for (int w = h0s[bj]; w < h1s[bj]; w++)
            sum += base[h*WW + w];
    P[gid] = sum / (float)((h1s[bi]-h0s[bi]) * (h1s[bj]-h0s[bj]));
}

// ---------------- launch ----------------
extern "C" void kernel_launch(void* const* d_in, const int* in_sizes, int n_in,
                              void* d_out, int out_size)
{
    const float* features = (const float*)d_in[0];
    const float* cell     = (const float*)d_in[1];
    const float* gaze     = (const float*)d_in[2];
    const float* w1  = (const float*)d_in[3];
    const float* b1  = (const float*)d_in[4];
    const float* w2  = (const float*)d_in[5];
    const float* b2  = (const float*)d_in[6];
    const float* wv  = (const float*)d_in[7];
    const float* bv  = (const float*)d_in[8];
    const float* ws1 = (const float*)d_in[9];
    const float* bs1 = (const float*)d_in[10];
    const float* ws2 = (const float*)d_in[11];
    const float* bs2 = (const float*)d_in[12];
    const float* ck1 = (const float*)d_in[13];
    const float* cb1 = (const float*)d_in[14];
    const float* ck2 = (const float*)d_in[15];
    const float* cb2 = (const float*)d_in[16];
    const float* wo  = (const float*)d_in[17];
    const float* bo  = (const float*)d_in[18];

    float* out = (float*)d_out;
    float* upd = out + (size_t)BB * 576;

    float *pX, *pC1, *pC2, *pWV, *pY2, *pP;
    __half *pUh, *pY1h, *pW1, *pW2;
    cudaGetSymbolAddress((void**)&pX,   g_X);
    cudaGetSymbolAddress((void**)&pC1,  g_C1);
    cudaGetSymbolAddress((void**)&pC2,  g_C2);
    cudaGetSymbolAddress((void**)&pWV,  g_WV);
    cudaGetSymbolAddress((void**)&pUh,  g_updh);
    cudaGetSymbolAddress((void**)&pY1h, g_Y1h);
    cudaGetSymbolAddress((void**)&pY2,  g_Y2);
    cudaGetSymbolAddress((void**)&pP,   g_P);
    cudaGetSymbolAddress((void**)&pW1,  g_W1h);
    cudaGetSymbolAddress((void**)&pW2,  g_W2h);

    prep_w1_kernel<<<(9*128*16 + 255)/256, 256>>>(ck1);
    prep_w2_kernel<<<(8*576*16 + 255)/256, 256>>>(ck2);

    build_x_kernel<<<BB, XDIM>>>(features, gaze, pX);
    gemm_kernel<<<dim3(4, BB/64), 256>>>(pX,  w1, b1, pC1, BB, 256, XDIM, 1);
    gemm_kernel<<<dim3(2, BB/64), 256>>>(pC1, w2, b2, pC2, BB, 128, 256, 1);
    gemm_kernel<<<dim3((WVDIM+63)/64, BB/64), 256>>>(pC2, wv, bv, pWV, BB, WVDIM, 128, 0);

    scatter_kernel<<<BB, 128>>>(cell, gaze, pWV, ws1, bs1, ws2, bs2, upd, pUh);

    conv1_hmma<<<dim3(4, BB), 512>>>(pUh, pW1, cb1, pY1h);
    conv2_hmma<<<dim3(4, BB), 256>>>(pY1h, pW2, cb2, pY2);

    pool_kernel<<<(BB*576 + 255)/256, 256>>>(pY2, pP);
    gemm_kernel<<<dim3(9, BB/64), 256>>>(pP, wo, bo, out, BB, 576, 576, 0);
}